// round 6
// baseline (speedup 1.0000x reference)
#include <cuda_runtime.h>
#include <cuda_bf16.h>
#include <cstdint>
#include <math.h>

#define NN 100000
#define DD 128
#define DOUT 8
#define EMAX 1600000
#define SCAN_BS 512
#define SCAN_NB ((NN + SCAN_BS - 1) / SCAN_BS)   // 196

// ---------------- scratch (static device globals; no allocation) ----------------
__device__ float g_y[NN * DD];
__device__ float g_z[NN * DD];
__device__ float g_h1[NN * DD];
__device__ float g_h2[NN * DD];
__device__ float g_y2[NN * DOUT];
__device__ float g_z2[NN * DOUT];
__device__ int   g_cnt[NN];
__device__ int   g_offs[NN + 1];
__device__ int   g_cursor[NN];
__device__ int   g_bsum[SCAN_NB];
__device__ int   g_csr[EMAX];

// ================= CSR build =================
__global__ void hist_kernel(const int* __restrict__ ei, int E, int* __restrict__ cnt) {
    int i = blockIdx.x * blockDim.x + threadIdx.x;
    if (i < E) atomicAdd(&cnt[ei[E + i]], 1);
}

__global__ void scan_block(const int* __restrict__ cnt, int* __restrict__ offs,
                           int* __restrict__ bsum) {
    __shared__ int sm[SCAN_BS];
    int i = blockIdx.x * SCAN_BS + threadIdx.x;
    int v = (i < NN) ? cnt[i] : 0;
    sm[threadIdx.x] = v;
    __syncthreads();
    #pragma unroll
    for (int d = 1; d < SCAN_BS; d <<= 1) {
        int t = (threadIdx.x >= d) ? sm[threadIdx.x - d] : 0;
        __syncthreads();
        sm[threadIdx.x] += t;
        __syncthreads();
    }
    if (i < NN) offs[i] = sm[threadIdx.x] - v;   // exclusive
    if (threadIdx.x == SCAN_BS - 1) bsum[blockIdx.x] = sm[threadIdx.x];
}

__global__ void scan_top(int* __restrict__ bsum) {
    __shared__ int sm[256];
    int i = threadIdx.x;
    int v = (i < SCAN_NB) ? bsum[i] : 0;
    sm[i] = v;
    __syncthreads();
    #pragma unroll
    for (int d = 1; d < 256; d <<= 1) {
        int t = (i >= d) ? sm[i - d] : 0;
        __syncthreads();
        sm[i] += t;
        __syncthreads();
    }
    if (i < SCAN_NB) bsum[i] = sm[i] - v;        // exclusive
}

__global__ void scan_add(int* __restrict__ offs, const int* __restrict__ bsum,
                         int* __restrict__ cursor, int E) {
    int i = blockIdx.x * blockDim.x + threadIdx.x;
    if (i < NN) {
        int v = offs[i] + bsum[i / SCAN_BS];
        offs[i] = v;
        cursor[i] = v;
    }
    if (i == 0) offs[NN] = E;
}

__global__ void fill_kernel(const int* __restrict__ ei, int E,
                            int* __restrict__ cursor, int* __restrict__ csr) {
    int e = blockIdx.x * blockDim.x + threadIdx.x;
    if (e < E) {
        int pos = atomicAdd(&cursor[ei[E + e]], 1);
        csr[pos] = ei[e];
    }
}

// ================ dual GEMM via bf16 tensor cores (split precision) ================
// C[128 x 256] = A[128 x 128] @ Wcat^T, Wcat = [Wl ; Wr] (256 x 128).
// a = ah + al (bf16 split); product = ah*bh + al*bh + ah*bl, fp32 accumulate.
#define AST 136
#define BST 136
#define A_ELEMS (128 * AST)                        // 17408
#define B_ELEMS (256 * BST)                        // 34816
#define SM_AH 0
#define SM_AL A_ELEMS
#define SM_BH (2 * A_ELEMS)
#define SM_BL (2 * A_ELEMS + B_ELEMS)
#define MMA_SMEM_BF16 (2 * A_ELEMS + 2 * B_ELEMS)  // 104448 elems
#define MMA_SMEM_BYTES (MMA_SMEM_BF16 * 2)         // 208896 bytes

// pre-converted weights (padded layout identical to smem: [n*BST + k])
__device__ __nv_bfloat16 g_wh[B_ELEMS];
__device__ __nv_bfloat16 g_wlo[B_ELEMS];

__global__ void convw_kernel(const float* __restrict__ Wl, const float* __restrict__ Wr,
                             __nv_bfloat16* __restrict__ Wh, __nv_bfloat16* __restrict__ Wlo) {
    int i = blockIdx.x * blockDim.x + threadIdx.x;  // 0..32767
    if (i >= 256 * 128) return;
    int n = i >> 7, k = i & 127;
    float w = (n < 128) ? Wl[i] : Wr[i - 16384];
    __nv_bfloat16 hi = __float2bfloat16(w);
    Wh[n * BST + k]  = hi;
    Wlo[n * BST + k] = __float2bfloat16(w - __bfloat162float(hi));
}

__device__ __forceinline__ void mma_bf16(float& c0, float& c1, float& c2, float& c3,
                                         uint32_t a0, uint32_t a1, uint32_t a2, uint32_t a3,
                                         uint32_t b0, uint32_t b1) {
    asm volatile(
        "mma.sync.aligned.m16n8k16.row.col.f32.bf16.bf16.f32 "
        "{%0,%1,%2,%3}, {%4,%5,%6,%7}, {%8,%9}, {%0,%1,%2,%3};"
        : "+f"(c0), "+f"(c1), "+f"(c2), "+f"(c3)
        : "r"(a0), "r"(a1), "r"(a2), "r"(a3), "r"(b0), "r"(b1));
}

__global__ __launch_bounds__(256, 1) void gemm_dual_mma(
    const float* __restrict__ H,
    const __nv_bfloat16* __restrict__ Wh, const __nv_bfloat16* __restrict__ Wlo,
    const float* __restrict__ bl,
    float* __restrict__ Y, float* __restrict__ Z, int nrows)
{
    extern __shared__ __nv_bfloat16 sb[];
    __nv_bfloat16* sAh = sb + SM_AH;
    __nv_bfloat16* sAl = sb + SM_AL;
    __nv_bfloat16* sBh = sb + SM_BH;
    __nv_bfloat16* sBl = sb + SM_BL;

    const int tid = threadIdx.x;
    const int row0 = blockIdx.x * 128;

    // ---- flat vectorized copy of pre-converted weights (4352 uint4 each) ----
    {
        const uint4* whg = (const uint4*)Wh;
        const uint4* wlg = (const uint4*)Wlo;
        uint4* sbh4 = (uint4*)sBh;
        uint4* sbl4 = (uint4*)sBl;
        #pragma unroll
        for (int j = 0; j < 17; j++) {
            int idx = tid + 256 * j;
            sbh4[idx] = whg[idx];
            sbl4[idx] = wlg[idx];
        }
    }
    // ---- A tile (128 rows x 128) -> smem bf16 hi/lo ----
    {
        const float4* H4 = (const float4*)H;
        #pragma unroll
        for (int j = 0; j < 16; j++) {
            int idx4 = tid + 256 * j;            // 4096 float4
            int r = idx4 >> 5, k4 = idx4 & 31;
            int row = row0 + r;
            float4 v = (row < nrows) ? __ldg(H4 + (long long)row * 32 + k4)
                                     : make_float4(0.f, 0.f, 0.f, 0.f);
            float av[4] = {v.x, v.y, v.z, v.w};
            unsigned short hb[4], lb[4];
            #pragma unroll
            for (int u = 0; u < 4; u++) {
                __nv_bfloat16 hi = __float2bfloat16(av[u]);
                hb[u] = __bfloat16_as_ushort(hi);
                lb[u] = __bfloat16_as_ushort(__float2bfloat16(av[u] - __bfloat162float(hi)));
            }
            int eoff = r * AST + k4 * 4;          // 8B aligned (AST = 136 = 8*17)
            uint2 uh = {(uint32_t)hb[0] | ((uint32_t)hb[1] << 16),
                        (uint32_t)hb[2] | ((uint32_t)hb[3] << 16)};
            uint2 ul = {(uint32_t)lb[0] | ((uint32_t)lb[1] << 16),
                        (uint32_t)lb[2] | ((uint32_t)lb[3] << 16)};
            *(uint2*)&sAh[eoff] = uh;
            *(uint2*)&sAl[eoff] = ul;
        }
    }
    __syncthreads();

    const int lane = tid & 31, wid = tid >> 5;
    const int wm = wid & 3, wn = wid >> 2;       // 4 warps along M, 2 along N
    const int m_base = wm * 32, n_base = wn * 128;
    const int g = lane >> 2, c2 = (lane & 3) * 2;

    float acc[2][16][4];
    #pragma unroll
    for (int mt = 0; mt < 2; mt++)
        #pragma unroll
        for (int nt = 0; nt < 16; nt++)
            #pragma unroll
            for (int u = 0; u < 4; u++) acc[mt][nt][u] = 0.0f;

    #pragma unroll
    for (int ks = 0; ks < 24; ks++) {
        const int seg = ks >> 3;
        const int k0 = (ks & 7) * 16;
        const __nv_bfloat16* As = (seg == 1) ? sAl : sAh;
        const __nv_bfloat16* Bs = (seg == 2) ? sBl : sBh;

        uint32_t a[2][4];
        #pragma unroll
        for (int mt = 0; mt < 2; mt++) {
            int base = (m_base + mt * 16 + g) * AST + k0 + c2;
            a[mt][0] = *(const uint32_t*)&As[base];
            a[mt][1] = *(const uint32_t*)&As[base + 8 * AST];
            a[mt][2] = *(const uint32_t*)&As[base + 8];
            a[mt][3] = *(const uint32_t*)&As[base + 8 * AST + 8];
        }

        #pragma unroll
        for (int nt = 0; nt < 16; nt++) {
            const __nv_bfloat16* bp = &Bs[(n_base + nt * 8 + g) * BST + k0 + c2];
            uint32_t b0 = *(const uint32_t*)bp;
            uint32_t b1 = *(const uint32_t*)(bp + 8);
            mma_bf16(acc[0][nt][0], acc[0][nt][1], acc[0][nt][2], acc[0][nt][3],
                     a[0][0], a[0][1], a[0][2], a[0][3], b0, b1);
            mma_bf16(acc[1][nt][0], acc[1][nt][1], acc[1][nt][2], acc[1][nt][3],
                     a[1][0], a[1][1], a[1][2], a[1][3], b0, b1);
        }
    }

    // ---- epilogue: n<128 -> Y, n>=128 -> Z (+bias) ----
    #pragma unroll
    for (int mt = 0; mt < 2; mt++) {
        const int row_a = row0 + m_base + mt * 16 + g;
        const int row_b = row_a + 8;
        #pragma unroll
        for (int nt = 0; nt < 16; nt++) {
            int n = n_base + nt * 8 + c2;
            float b0v = 0.0f, b1v = 0.0f;
            float* O;
            int col;
            if (n < 128) { O = Y; col = n; }
            else { O = Z; col = n - 128; b0v = __ldg(&bl[col]); b1v = __ldg(&bl[col + 1]); }
            if (row_a < nrows) {
                float2 v = {acc[mt][nt][0] + b0v, acc[mt][nt][1] + b1v};
                *(float2*)&O[(long long)row_a * 128 + col] = v;
            }
            if (row_b < nrows) {
                float2 v = {acc[mt][nt][2] + b0v, acc[mt][nt][3] + b1v};
                *(float2*)&O[(long long)row_b * 128 + col] = v;
            }
        }
    }
}

// ---------------- small GEMM for layer 2 ----------------
__global__ __launch_bounds__(256) void gemm_small(
    const float* __restrict__ H, const float* __restrict__ Wl,
    const float* __restrict__ Wr, const float* __restrict__ bl,
    float* __restrict__ Y, float* __restrict__ Z)
{
    __shared__ float sW[128 * 16];
    __shared__ float sH[16 * 128];

    const int tid = threadIdx.x;
    #pragma unroll
    for (int j = 0; j < 8; j++) {
        int idx = tid + 256 * j;
        int o = idx & 15, k = idx >> 4;
        sW[k * 16 + o] = (o < 8) ? Wl[o * 128 + k] : Wr[(o - 8) * 128 + k];
    }
    const int row0 = blockIdx.x * 16;
    #pragma unroll
    for (int j = 0; j < 8; j++) {
        int idx = tid + 256 * j;
        int r = idx >> 7, k = idx & 127;
        int row = row0 + r;
        sH[r * 128 + k] = (row < NN) ? H[(long long)row * 128 + k] : 0.0f;
    }
    __syncthreads();

    const int o = tid & 15, rl = tid >> 4;
    float acc = 0.0f;
    #pragma unroll 8
    for (int k = 0; k < 128; k++)
        acc = fmaf(sH[rl * 128 + k], sW[k * 16 + o], acc);

    int row = row0 + rl;
    if (row < NN) {
        if (o < 8) Y[row * 8 + o] = acc;
        else       Z[row * 8 + (o - 8)] = acc + __ldg(&bl[o - 8]);
    }
}

// ========== gather aggregate d=128 ==========
__global__ __launch_bounds__(256) void gather128(
    const int* __restrict__ csr, const int* __restrict__ offs,
    const float* __restrict__ Y, const float* __restrict__ Z,
    float* __restrict__ H)
{
    int node = blockIdx.x * 8 + (threadIdx.x >> 5);
    if (node >= NN) return;
    int lane = threadIdx.x & 31;
    int beg = offs[node], end = offs[node + 1];

    float4 acc = {0.0f, 0.0f, 0.0f, 0.0f};
    const float4* Y4 = (const float4*)Y;

    for (int j = beg; j < end; j += 32) {
        int chunk = min(32, end - j);
        int id = (lane < chunk) ? csr[j + lane] : 0;
        int t = 0;
        for (; t + 4 <= chunk; t += 4) {
            int s0 = __shfl_sync(0xffffffffu, id, t);
            int s1 = __shfl_sync(0xffffffffu, id, t + 1);
            int s2 = __shfl_sync(0xffffffffu, id, t + 2);
            int s3 = __shfl_sync(0xffffffffu, id, t + 3);
            float4 v0 = __ldg(Y4 + s0 * 32 + lane);
            float4 v1 = __ldg(Y4 + s1 * 32 + lane);
            float4 v2 = __ldg(Y4 + s2 * 32 + lane);
            float4 v3 = __ldg(Y4 + s3 * 32 + lane);
            acc.x += v0.x + v1.x + v2.x + v3.x;
            acc.y += v0.y + v1.y + v2.y + v3.y;
            acc.z += v0.z + v1.z + v2.z + v3.z;
            acc.w += v0.w + v1.w + v2.w + v3.w;
        }
        for (; t < chunk; t++) {
            int s = __shfl_sync(0xffffffffu, id, t);
            float4 v = __ldg(Y4 + s * 32 + lane);
            acc.x += v.x; acc.y += v.y; acc.z += v.z; acc.w += v.w;
        }
    }

    float iv = 1.0f / (float)max(end - beg, 1);
    float4 z = __ldg((const float4*)Z + node * 32 + lane);
    float4 v;
    v.x = fmaxf(fmaf(acc.x, iv, z.x), 0.0f);
    v.y = fmaxf(fmaf(acc.y, iv, z.y), 0.0f);
    v.z = fmaxf(fmaf(acc.z, iv, z.z), 0.0f);
    v.w = fmaxf(fmaf(acc.w, iv, z.w), 0.0f);
    ((float4*)H)[node * 32 + lane] = v;
}

// ========== gather d=8 + finalize + log_softmax ==========
__global__ __launch_bounds__(256) void gather8(
    const int* __restrict__ csr, const int* __restrict__ offs,
    const float* __restrict__ Y, const float* __restrict__ Z,
    float* __restrict__ outh, float* __restrict__ outls)
{
    int node = blockIdx.x * 64 + (threadIdx.x >> 2);
    if (node >= NN) return;
    int lane4 = threadIdx.x & 3;
    int beg = offs[node], end = offs[node + 1];

    float a[8] = {0, 0, 0, 0, 0, 0, 0, 0};
    const float4* Y4 = (const float4*)Y;
    for (int j = beg + lane4; j < end; j += 4) {
        int s = csr[j];
        float4 v0 = __ldg(Y4 + s * 2);
        float4 v1 = __ldg(Y4 + s * 2 + 1);
        a[0] += v0.x; a[1] += v0.y; a[2] += v0.z; a[3] += v0.w;
        a[4] += v1.x; a[5] += v1.y; a[6] += v1.z; a[7] += v1.w;
    }
    #pragma unroll
    for (int i = 0; i < 8; i++) {
        a[i] += __shfl_xor_sync(0xffffffffu, a[i], 1);
        a[i] += __shfl_xor_sync(0xffffffffu, a[i], 2);
    }
    if (lane4 != 0) return;

    float iv = 1.0f / (float)max(end - beg, 1);
    float4 z0 = __ldg((const float4*)Z + node * 2);
    float4 z1 = __ldg((const float4*)Z + node * 2 + 1);
    float h[8];
    h[0] = fmaf(a[0], iv, z0.x); h[1] = fmaf(a[1], iv, z0.y);
    h[2] = fmaf(a[2], iv, z0.z); h[3] = fmaf(a[3], iv, z0.w);
    h[4] = fmaf(a[4], iv, z1.x); h[5] = fmaf(a[5], iv, z1.y);
    h[6] = fmaf(a[6], iv, z1.z); h[7] = fmaf(a[7], iv, z1.w);

    ((float4*)outh)[node * 2]     = make_float4(h[0], h[1], h[2], h[3]);
    ((float4*)outh)[node * 2 + 1] = make_float4(h[4], h[5], h[6], h[7]);

    if (outls) {
        float m = h[0];
        #pragma unroll
        for (int j = 1; j < 8; j++) m = fmaxf(m, h[j]);
        float sum = 0.0f;
        #pragma unroll
        for (int j = 0; j < 8; j++) sum += expf(h[j] - m);
        float lse = logf(sum) + m;
        ((float4*)outls)[node * 2]     = make_float4(h[0]-lse, h[1]-lse, h[2]-lse, h[3]-lse);
        ((float4*)outls)[node * 2 + 1] = make_float4(h[4]-lse, h[5]-lse, h[6]-lse, h[7]-lse);
    }
}

// ---------------- launch ----------------
extern "C" void kernel_launch(void* const* d_in, const int* in_sizes, int n_in,
                              void* d_out, int out_size)
{
    const float* x   = (const float*)d_in[0];
    const int*   ei  = (const int*)d_in[1];   // int32 (JAX default downcasts int64)
    const float* Wl0 = (const float*)d_in[2];
    const float* bl0 = (const float*)d_in[3];
    const float* Wr0 = (const float*)d_in[4];
    const float* Wl1 = (const float*)d_in[5];
    const float* bl1 = (const float*)d_in[6];
    const float* Wr1 = (const float*)d_in[7];
    const float* Wl2 = (const float*)d_in[8];
    const float* bl2 = (const float*)d_in[9];
    const float* Wr2 = (const float*)d_in[10];
    int E = in_sizes[1] / 2;
    if (E > EMAX) E = EMAX;
    float* out = (float*)d_out;

    void *py, *pz, *ph1, *ph2, *py2, *pz2, *pcnt, *poffs, *pcur, *pbsum, *pcsr, *pwh, *pwl;
    cudaGetSymbolAddress(&py,   g_y);
    cudaGetSymbolAddress(&pz,   g_z);
    cudaGetSymbolAddress(&ph1,  g_h1);
    cudaGetSymbolAddress(&ph2,  g_h2);
    cudaGetSymbolAddress(&py2,  g_y2);
    cudaGetSymbolAddress(&pz2,  g_z2);
    cudaGetSymbolAddress(&pcnt, g_cnt);
    cudaGetSymbolAddress(&poffs,g_offs);
    cudaGetSymbolAddress(&pcur, g_cursor);
    cudaGetSymbolAddress(&pbsum,g_bsum);
    cudaGetSymbolAddress(&pcsr, g_csr);
    cudaGetSymbolAddress(&pwh,  g_wh);
    cudaGetSymbolAddress(&pwl,  g_wlo);

    cudaFuncSetAttribute(gemm_dual_mma, cudaFuncAttributeMaxDynamicSharedMemorySize, MMA_SMEM_BYTES);

    const int tiles = (NN + 127) / 128;

    // ---- build CSR (dst-major) ----
    cudaMemsetAsync(pcnt, 0, NN * sizeof(int));
    hist_kernel<<<(E + 255) / 256, 256>>>(ei, E, (int*)pcnt);
    scan_block<<<SCAN_NB, SCAN_BS>>>((const int*)pcnt, (int*)poffs, (int*)pbsum);
    scan_top<<<1, 256>>>((int*)pbsum);
    scan_add<<<(NN + 255) / 256, 256>>>((int*)poffs, (const int*)pbsum, (int*)pcur, E);
    fill_kernel<<<(E + 255) / 256, 256>>>(ei, E, (int*)pcur, (int*)pcsr);

    // ---- layer 0: x -> h1 ----
    convw_kernel<<<128, 256>>>(Wl0, Wr0, (__nv_bfloat16*)pwh, (__nv_bfloat16*)pwl);
    gemm_dual_mma<<<tiles, 256, MMA_SMEM_BYTES>>>(x, (const __nv_bfloat16*)pwh,
                                                  (const __nv_bfloat16*)pwl, bl0,
                                                  (float*)py, (float*)pz, NN);
    gather128<<<(NN + 7) / 8, 256>>>((const int*)pcsr, (const int*)poffs,
                                     (const float*)py, (const float*)pz, (float*)ph1);

    // ---- layer 1: h1 -> h2 ----
    convw_kernel<<<128, 256>>>(Wl1, Wr1, (__nv_bfloat16*)pwh, (__nv_bfloat16*)pwl);
    gemm_dual_mma<<<tiles, 256, MMA_SMEM_BYTES>>>((const float*)ph1, (const __nv_bfloat16*)pwh,
                                                  (const __nv_bfloat16*)pwl, bl1,
                                                  (float*)py, (float*)pz, NN);
    gather128<<<(NN + 7) / 8, 256>>>((const int*)pcsr, (const int*)poffs,
                                     (const float*)py, (const float*)pz, (float*)ph2);

    // ---- layer 2: h2 -> out ----
    gemm_small<<<(NN + 15) / 16, 256>>>((const float*)ph2, Wl2, Wr2, bl2,
                                        (float*)py2, (float*)pz2);
    float* outls = (out_size >= 2 * NN * DOUT) ? (out + (size_t)NN * DOUT) : nullptr;
    gather8<<<(NN + 63) / 64, 256>>>((const int*)pcsr, (const int*)poffs,
                                     (const float*)py2, (const float*)pz2, out, outls);
}

// round 9
// speedup vs baseline: 1.0281x; 1.0281x over previous
#include <cuda_runtime.h>
#include <cuda_bf16.h>
#include <cstdint>
#include <math.h>

#define NN 100000
#define DD 128
#define DOUT 8
#define EMAX 1600000
#define SCAN_BS 512
#define SCAN_NB ((NN + SCAN_BS - 1) / SCAN_BS)   // 196

// ---------------- scratch (static device globals; no allocation) ----------------
__device__ float g_y[NN * DD];
__device__ float g_z[NN * DD];
__device__ float g_h1[NN * DD];
__device__ float g_h2[NN * DD];
__device__ float g_y2[NN * DOUT];
__device__ float g_z2[NN * DOUT];
__device__ int   g_cnt[NN];
__device__ int   g_offs[NN + 1];
__device__ int   g_cursor[NN];
__device__ int   g_bsum[SCAN_NB];
__device__ int   g_csr[EMAX];

// ================= CSR build =================
__global__ void hist_kernel(const int* __restrict__ ei, int E, int* __restrict__ cnt) {
    int i = blockIdx.x * blockDim.x + threadIdx.x;
    if (i < E) atomicAdd(&cnt[ei[E + i]], 1);
}

__global__ void scan_block(const int* __restrict__ cnt, int* __restrict__ offs,
                           int* __restrict__ bsum) {
    __shared__ int sm[SCAN_BS];
    int i = blockIdx.x * SCAN_BS + threadIdx.x;
    int v = (i < NN) ? cnt[i] : 0;
    sm[threadIdx.x] = v;
    __syncthreads();
    #pragma unroll
    for (int d = 1; d < SCAN_BS; d <<= 1) {
        int t = (threadIdx.x >= d) ? sm[threadIdx.x - d] : 0;
        __syncthreads();
        sm[threadIdx.x] += t;
        __syncthreads();
    }
    if (i < NN) offs[i] = sm[threadIdx.x] - v;   // exclusive
    if (threadIdx.x == SCAN_BS - 1) bsum[blockIdx.x] = sm[threadIdx.x];
}

__global__ void scan_top(int* __restrict__ bsum) {
    __shared__ int sm[256];
    int i = threadIdx.x;
    int v = (i < SCAN_NB) ? bsum[i] : 0;
    sm[i] = v;
    __syncthreads();
    #pragma unroll
    for (int d = 1; d < 256; d <<= 1) {
        int t = (i >= d) ? sm[i - d] : 0;
        __syncthreads();
        sm[i] += t;
        __syncthreads();
    }
    if (i < SCAN_NB) bsum[i] = sm[i] - v;        // exclusive
}

__global__ void scan_add(int* __restrict__ offs, const int* __restrict__ bsum,
                         int* __restrict__ cursor, int E) {
    int i = blockIdx.x * blockDim.x + threadIdx.x;
    if (i < NN) {
        int v = offs[i] + bsum[i / SCAN_BS];
        offs[i] = v;
        cursor[i] = v;
    }
    if (i == 0) offs[NN] = E;
}

__global__ void fill_kernel(const int* __restrict__ ei, int E,
                            int* __restrict__ cursor, int* __restrict__ csr) {
    int e = blockIdx.x * blockDim.x + threadIdx.x;
    if (e < E) {
        int pos = atomicAdd(&cursor[ei[E + e]], 1);
        csr[pos] = ei[e];
    }
}

// ================ dual GEMM via bf16 tensor cores (split precision, N-split) ================
// blockIdx.y = 0: C[64x128] = A @ Wl^T -> Y.   blockIdx.y = 1: C = A @ Wr^T + bl -> Z.
// a = ah + al (bf16 split); product = ah*bh + al*bh + ah*bl, fp32 accumulate.
#define AST 136
#define BST 136
#define A_ELEMS (64 * AST)                         // 8704
#define BH_ELEMS (128 * BST)                       // 17408 bf16 per half = 2176 uint4
#define SM_AH 0
#define SM_AL A_ELEMS
#define SM_BH (2 * A_ELEMS)
#define SM_BL (2 * A_ELEMS + BH_ELEMS)
#define MMA_SMEM_BF16 (2 * A_ELEMS + 2 * BH_ELEMS) // 52224 elems
#define MMA_SMEM_BYTES (MMA_SMEM_BF16 * 2)         // 104448 bytes -> 2 blocks/SM

// pre-converted weights (padded layout identical to smem: [n*BST + k], n<128 Wl, n>=128 Wr)
__device__ __nv_bfloat16 g_wh[256 * BST];
__device__ __nv_bfloat16 g_wlo[256 * BST];

__global__ void convw_kernel(const float* __restrict__ Wl, const float* __restrict__ Wr,
                             __nv_bfloat16* __restrict__ Wh, __nv_bfloat16* __restrict__ Wlo) {
    int i = blockIdx.x * blockDim.x + threadIdx.x;  // 0..32767
    if (i >= 256 * 128) return;
    int n = i >> 7, k = i & 127;
    float w = (n < 128) ? Wl[i] : Wr[i - 16384];
    __nv_bfloat16 hi = __float2bfloat16(w);
    Wh[n * BST + k]  = hi;
    Wlo[n * BST + k] = __float2bfloat16(w - __bfloat162float(hi));
}

__device__ __forceinline__ void mma_bf16(float& c0, float& c1, float& c2, float& c3,
                                         uint32_t a0, uint32_t a1, uint32_t a2, uint32_t a3,
                                         uint32_t b0, uint32_t b1) {
    asm volatile(
        "mma.sync.aligned.m16n8k16.row.col.f32.bf16.bf16.f32 "
        "{%0,%1,%2,%3}, {%4,%5,%6,%7}, {%8,%9}, {%0,%1,%2,%3};"
        : "+f"(c0), "+f"(c1), "+f"(c2), "+f"(c3)
        : "r"(a0), "r"(a1), "r"(a2), "r"(a3), "r"(b0), "r"(b1));
}

__global__ __launch_bounds__(256, 2) void gemm_dual_mma(
    const float* __restrict__ H,
    const __nv_bfloat16* __restrict__ Wh, const __nv_bfloat16* __restrict__ Wlo,
    const float* __restrict__ bl,
    float* __restrict__ Y, float* __restrict__ Z, int nrows)
{
    extern __shared__ __nv_bfloat16 sb[];
    __nv_bfloat16* sAh = sb + SM_AH;
    __nv_bfloat16* sAl = sb + SM_AL;
    __nv_bfloat16* sBh = sb + SM_BH;
    __nv_bfloat16* sBl = sb + SM_BL;

    const int tid = threadIdx.x;
    const int row0 = blockIdx.x * 64;
    const int half = blockIdx.y;                 // 0 -> Y (Wl), 1 -> Z (Wr + bias)

    // ---- flat vectorized copy of this half's pre-converted weights ----
    // BH_ELEMS/8 = 2176 uint4 per buffer -> 9 iterations of 256 threads (guarded).
    {
        const uint4* whg = (const uint4*)(Wh + half * BH_ELEMS);
        const uint4* wlg = (const uint4*)(Wlo + half * BH_ELEMS);
        uint4* sbh4 = (uint4*)sBh;
        uint4* sbl4 = (uint4*)sBl;
        #pragma unroll
        for (int j = 0; j < 9; j++) {
            int idx = tid + 256 * j;
            if (idx < BH_ELEMS / 8) {
                sbh4[idx] = whg[idx];
                sbl4[idx] = wlg[idx];
            }
        }
    }
    // ---- A tile (64 rows x 128) -> smem bf16 hi/lo ----
    {
        const float4* H4 = (const float4*)H;
        #pragma unroll
        for (int j = 0; j < 8; j++) {
            int idx4 = tid + 256 * j;            // 2048 float4
            int r = idx4 >> 5, k4 = idx4 & 31;
            int row = row0 + r;
            float4 v = (row < nrows) ? __ldg(H4 + (long long)row * 32 + k4)
                                     : make_float4(0.f, 0.f, 0.f, 0.f);
            float av[4] = {v.x, v.y, v.z, v.w};
            unsigned short hb[4], lb[4];
            #pragma unroll
            for (int u = 0; u < 4; u++) {
                __nv_bfloat16 hi = __float2bfloat16(av[u]);
                hb[u] = __bfloat16_as_ushort(hi);
                lb[u] = __bfloat16_as_ushort(__float2bfloat16(av[u] - __bfloat162float(hi)));
            }
            int eoff = r * AST + k4 * 4;         // 8B aligned (AST = 136 = 8*17)
            uint2 uh = {(uint32_t)hb[0] | ((uint32_t)hb[1] << 16),
                        (uint32_t)hb[2] | ((uint32_t)hb[3] << 16)};
            uint2 ul = {(uint32_t)lb[0] | ((uint32_t)lb[1] << 16),
                        (uint32_t)lb[2] | ((uint32_t)lb[3] << 16)};
            *(uint2*)&sAh[eoff] = uh;
            *(uint2*)&sAl[eoff] = ul;
        }
    }
    __syncthreads();

    const int lane = tid & 31, wid = tid >> 5;
    const int wm = wid & 1, wn = wid >> 1;       // 2 warps along M, 4 along N
    const int m_base = wm * 32, n_base = wn * 32;
    const int g = lane >> 2, c2 = (lane & 3) * 2;

    float acc[2][4][4];
    #pragma unroll
    for (int mt = 0; mt < 2; mt++)
        #pragma unroll
        for (int nt = 0; nt < 4; nt++)
            #pragma unroll
            for (int u = 0; u < 4; u++) acc[mt][nt][u] = 0.0f;

    #pragma unroll
    for (int ks = 0; ks < 24; ks++) {
        const int seg = ks >> 3;
        const int k0 = (ks & 7) * 16;
        const __nv_bfloat16* As = (seg == 1) ? sAl : sAh;
        const __nv_bfloat16* Bs = (seg == 2) ? sBl : sBh;

        uint32_t a[2][4];
        #pragma unroll
        for (int mt = 0; mt < 2; mt++) {
            int base = (m_base + mt * 16 + g) * AST + k0 + c2;
            a[mt][0] = *(const uint32_t*)&As[base];
            a[mt][1] = *(const uint32_t*)&As[base + 8 * AST];
            a[mt][2] = *(const uint32_t*)&As[base + 8];
            a[mt][3] = *(const uint32_t*)&As[base + 8 * AST + 8];
        }

        #pragma unroll
        for (int nt = 0; nt < 4; nt++) {
            const __nv_bfloat16* bp = &Bs[(n_base + nt * 8 + g) * BST + k0 + c2];
            uint32_t b0 = *(const uint32_t*)bp;
            uint32_t b1 = *(const uint32_t*)(bp + 8);
            mma_bf16(acc[0][nt][0], acc[0][nt][1], acc[0][nt][2], acc[0][nt][3],
                     a[0][0], a[0][1], a[0][2], a[0][3], b0, b1);
            mma_bf16(acc[1][nt][0], acc[1][nt][1], acc[1][nt][2], acc[1][nt][3],
                     a[1][0], a[1][1], a[1][2], a[1][3], b0, b1);
        }
    }

    // ---- epilogue ----
    float* O = half ? Z : Y;
    #pragma unroll
    for (int mt = 0; mt < 2; mt++) {
        const int row_a = row0 + m_base + mt * 16 + g;
        const int row_b = row_a + 8;
        #pragma unroll
        for (int nt = 0; nt < 4; nt++) {
            int col = n_base + nt * 8 + c2;
            float b0v = 0.0f, b1v = 0.0f;
            if (half) { b0v = __ldg(&bl[col]); b1v = __ldg(&bl[col + 1]); }
            if (row_a < nrows) {
                float2 v = {acc[mt][nt][0] + b0v, acc[mt][nt][1] + b1v};
                *(float2*)&O[(long long)row_a * 128 + col] = v;
            }
            if (row_b < nrows) {
                float2 v = {acc[mt][nt][2] + b0v, acc[mt][nt][3] + b1v};
                *(float2*)&O[(long long)row_b * 128 + col] = v;
            }
        }
    }
}

// ---------------- small GEMM for layer 2 ----------------
__global__ __launch_bounds__(256) void gemm_small(
    const float* __restrict__ H, const float* __restrict__ Wl,
    const float* __restrict__ Wr, const float* __restrict__ bl,
    float* __restrict__ Y, float* __restrict__ Z)
{
    __shared__ float sW[128 * 16];
    __shared__ float sH[16 * 128];

    const int tid = threadIdx.x;
    #pragma unroll
    for (int j = 0; j < 8; j++) {
        int idx = tid + 256 * j;
        int o = idx & 15, k = idx >> 4;
        sW[k * 16 + o] = (o < 8) ? Wl[o * 128 + k] : Wr[(o - 8) * 128 + k];
    }
    const int row0 = blockIdx.x * 16;
    #pragma unroll
    for (int j = 0; j < 8; j++) {
        int idx = tid + 256 * j;
        int r = idx >> 7, k = idx & 127;
        int row = row0 + r;
        sH[r * 128 + k] = (row < NN) ? H[(long long)row * 128 + k] : 0.0f;
    }
    __syncthreads();

    const int o = tid & 15, rl = tid >> 4;
    float acc = 0.0f;
    #pragma unroll 8
    for (int k = 0; k < 128; k++)
        acc = fmaf(sH[rl * 128 + k], sW[k * 16 + o], acc);

    int row = row0 + rl;
    if (row < NN) {
        if (o < 8) Y[row * 8 + o] = acc;
        else       Z[row * 8 + (o - 8)] = acc + __ldg(&bl[o - 8]);
    }
}

// ========== gather aggregate d=128 ==========
__global__ __launch_bounds__(256) void gather128(
    const int* __restrict__ csr, const int* __restrict__ offs,
    const float* __restrict__ Y, const float* __restrict__ Z,
    float* __restrict__ H)
{
    int node = blockIdx.x * 8 + (threadIdx.x >> 5);
    if (node >= NN) return;
    int lane = threadIdx.x & 31;
    int beg = offs[node], end = offs[node + 1];

    float4 acc = {0.0f, 0.0f, 0.0f, 0.0f};
    const float4* Y4 = (const float4*)Y;

    for (int j = beg; j < end; j += 32) {
        int chunk = min(32, end - j);
        int id = (lane < chunk) ? csr[j + lane] : 0;
        int t = 0;
        for (; t + 4 <= chunk; t += 4) {
            int s0 = __shfl_sync(0xffffffffu, id, t);
            int s1 = __shfl_sync(0xffffffffu, id, t + 1);
            int s2 = __shfl_sync(0xffffffffu, id, t + 2);
            int s3 = __shfl_sync(0xffffffffu, id, t + 3);
            float4 v0 = __ldg(Y4 + s0 * 32 + lane);
            float4 v1 = __ldg(Y4 + s1 * 32 + lane);
            float4 v2 = __ldg(Y4 + s2 * 32 + lane);
            float4 v3 = __ldg(Y4 + s3 * 32 + lane);
            acc.x += v0.x + v1.x + v2.x + v3.x;
            acc.y += v0.y + v1.y + v2.y + v3.y;
            acc.z += v0.z + v1.z + v2.z + v3.z;
            acc.w += v0.w + v1.w + v2.w + v3.w;
        }
        for (; t < chunk; t++) {
            int s = __shfl_sync(0xffffffffu, id, t);
            float4 v = __ldg(Y4 + s * 32 + lane);
            acc.x += v.x; acc.y += v.y; acc.z += v.z; acc.w += v.w;
        }
    }

    float iv = 1.0f / (float)max(end - beg, 1);
    float4 z = __ldg((const float4*)Z + node * 32 + lane);
    float4 v;
    v.x = fmaxf(fmaf(acc.x, iv, z.x), 0.0f);
    v.y = fmaxf(fmaf(acc.y, iv, z.y), 0.0f);
    v.z = fmaxf(fmaf(acc.z, iv, z.z), 0.0f);
    v.w = fmaxf(fmaf(acc.w, iv, z.w), 0.0f);
    ((float4*)H)[node * 32 + lane] = v;
}

// ========== gather d=8 + finalize + log_softmax ==========
__global__ __launch_bounds__(256) void gather8(
    const int* __restrict__ csr, const int* __restrict__ offs,
    const float* __restrict__ Y, const float* __restrict__ Z,
    float* __restrict__ outh, float* __restrict__ outls)
{
    int node = blockIdx.x * 64 + (threadIdx.x >> 2);
    if (node >= NN) return;
    int lane4 = threadIdx.x & 3;
    int beg = offs[node], end = offs[node + 1];

    float a[8] = {0, 0, 0, 0, 0, 0, 0, 0};
    const float4* Y4 = (const float4*)Y;
    for (int j = beg + lane4; j < end; j += 4) {
        int s = csr[j];
        float4 v0 = __ldg(Y4 + s * 2);
        float4 v1 = __ldg(Y4 + s * 2 + 1);
        a[0] += v0.x; a[1] += v0.y; a[2] += v0.z; a[3] += v0.w;
        a[4] += v1.x; a[5] += v1.y; a[6] += v1.z; a[7] += v1.w;
    }
    #pragma unroll
    for (int i = 0; i < 8; i++) {
        a[i] += __shfl_xor_sync(0xffffffffu, a[i], 1);
        a[i] += __shfl_xor_sync(0xffffffffu, a[i], 2);
    }
    if (lane4 != 0) return;

    float iv = 1.0f / (float)max(end - beg, 1);
    float4 z0 = __ldg((const float4*)Z + node * 2);
    float4 z1 = __ldg((const float4*)Z + node * 2 + 1);
    float h[8];
    h[0] = fmaf(a[0], iv, z0.x); h[1] = fmaf(a[1], iv, z0.y);
    h[2] = fmaf(a[2], iv, z0.z); h[3] = fmaf(a[3], iv, z0.w);
    h[4] = fmaf(a[4], iv, z1.x); h[5] = fmaf(a[5], iv, z1.y);
    h[6] = fmaf(a[6], iv, z1.z); h[7] = fmaf(a[7], iv, z1.w);

    ((float4*)outh)[node * 2]     = make_float4(h[0], h[1], h[2], h[3]);
    ((float4*)outh)[node * 2 + 1] = make_float4(h[4], h[5], h[6], h[7]);

    if (outls) {
        float m = h[0];
        #pragma unroll
        for (int j = 1; j < 8; j++) m = fmaxf(m, h[j]);
        float sum = 0.0f;
        #pragma unroll
        for (int j = 0; j < 8; j++) sum += expf(h[j] - m);
        float lse = logf(sum) + m;
        ((float4*)outls)[node * 2]     = make_float4(h[0]-lse, h[1]-lse, h[2]-lse, h[3]-lse);
        ((float4*)outls)[node * 2 + 1] = make_float4(h[4]-lse, h[5]-lse, h[6]-lse, h[7]-lse);
    }
}

// ---------------- launch ----------------
extern "C" void kernel_launch(void* const* d_in, const int* in_sizes, int n_in,
                              void* d_out, int out_size)
{
    const float* x   = (const float*)d_in[0];
    const int*   ei  = (const int*)d_in[1];   // int32 (JAX default downcasts int64)
    const float* Wl0 = (const float*)d_in[2];
    const float* bl0 = (const float*)d_in[3];
    const float* Wr0 = (const float*)d_in[4];
    const float* Wl1 = (const float*)d_in[5];
    const float* bl1 = (const float*)d_in[6];
    const float* Wr1 = (const float*)d_in[7];
    const float* Wl2 = (const float*)d_in[8];
    const float* bl2 = (const float*)d_in[9];
    const float* Wr2 = (const float*)d_in[10];
    int E = in_sizes[1] / 2;
    if (E > EMAX) E = EMAX;
    float* out = (float*)d_out;

    void *py, *pz, *ph1, *ph2, *py2, *pz2, *pcnt, *poffs, *pcur, *pbsum, *pcsr, *pwh, *pwl;
    cudaGetSymbolAddress(&py,   g_y);
    cudaGetSymbolAddress(&pz,   g_z);
    cudaGetSymbolAddress(&ph1,  g_h1);
    cudaGetSymbolAddress(&ph2,  g_h2);
    cudaGetSymbolAddress(&py2,  g_y2);
    cudaGetSymbolAddress(&pz2,  g_z2);
    cudaGetSymbolAddress(&pcnt, g_cnt);
    cudaGetSymbolAddress(&poffs,g_offs);
    cudaGetSymbolAddress(&pcur, g_cursor);
    cudaGetSymbolAddress(&pbsum,g_bsum);
    cudaGetSymbolAddress(&pcsr, g_csr);
    cudaGetSymbolAddress(&pwh,  g_wh);
    cudaGetSymbolAddress(&pwl,  g_wlo);

    cudaFuncSetAttribute(gemm_dual_mma, cudaFuncAttributeMaxDynamicSharedMemorySize, MMA_SMEM_BYTES);

    const dim3 gemm_grid((NN + 63) / 64, 2);

    // ---- build CSR (dst-major) ----
    cudaMemsetAsync(pcnt, 0, NN * sizeof(int));
    hist_kernel<<<(E + 255) / 256, 256>>>(ei, E, (int*)pcnt);
    scan_block<<<SCAN_NB, SCAN_BS>>>((const int*)pcnt, (int*)poffs, (int*)pbsum);
    scan_top<<<1, 256>>>((int*)pbsum);
    scan_add<<<(NN + 255) / 256, 256>>>((int*)poffs, (const int*)pbsum, (int*)pcur, E);
    fill_kernel<<<(E + 255) / 256, 256>>>(ei, E, (int*)pcur, (int*)pcsr);

    // ---- layer 0: x -> h1 ----
    convw_kernel<<<128, 256>>>(Wl0, Wr0, (__nv_bfloat16*)pwh, (__nv_bfloat16*)pwl);
    gemm_dual_mma<<<gemm_grid, 256, MMA_SMEM_BYTES>>>(x, (const __nv_bfloat16*)pwh,
                                                      (const __nv_bfloat16*)pwl, bl0,
                                                      (float*)py, (float*)pz, NN);
    gather128<<<(NN + 7) / 8, 256>>>((const int*)pcsr, (const int*)poffs,
                                     (const float*)py, (const float*)pz, (float*)ph1);

    // ---- layer 1: h1 -> h2 ----
    convw_kernel<<<128, 256>>>(Wl1, Wr1, (__nv_bfloat16*)pwh, (__nv_bfloat16*)pwl);
    gemm_dual_mma<<<gemm_grid, 256, MMA_SMEM_BYTES>>>((const float*)ph1, (const __nv_bfloat16*)pwh,
                                                      (const __nv_bfloat16*)pwl, bl1,
                                                      (float*)py, (float*)pz, NN);
    gather128<<<(NN + 7) / 8, 256>>>((const int*)pcsr, (const int*)poffs,
                                     (const float*)py, (const float*)pz, (float*)ph2);

    // ---- layer 2: h2 -> out ----
    gemm_small<<<(NN + 15) / 16, 256>>>((const float*)ph2, Wl2, Wr2, bl2,
                                        (float*)py2, (float*)pz2);
    float* outls = (out_size >= 2 * NN * DOUT) ? (out + (size_t)NN * DOUT) : nullptr;
    gather8<<<(NN + 63) / 64, 256>>>((const int*)pcsr, (const int*)poffs,
                                     (const float*)py2, (const float*)pz2, out, outls);
}

// round 10
// speedup vs baseline: 1.0894x; 1.0596x over previous
#include <cuda_runtime.h>
#include <cuda_bf16.h>
#include <cstdint>
#include <math.h>

#define NN 100000
#define DD 128
#define DOUT 8
#define EMAX 1600000
#define SCAN_BS 512
#define SCAN_NB ((NN + SCAN_BS - 1) / SCAN_BS)   // 196
#define NTILES ((NN + 63) / 64)                  // 1563

// ---------------- scratch (static device globals; no allocation) ----------------
__device__ float g_y[NN * DD];
__device__ float g_z[NN * DD];
__device__ float g_y2[NN * DOUT];
__device__ float g_z2[NN * DOUT];
__device__ int   g_cnt[NN];
__device__ int   g_offs[NN + 1];
__device__ int   g_cursor[NN];
__device__ int   g_bsum[SCAN_NB];
__device__ int   g_csr[EMAX];
// bf16 hi/lo operand arrays for GEMM A (x, then h1, then h2), layout [row*128 + k]
__device__ __nv_bfloat16 g_ah[NN * DD];
__device__ __nv_bfloat16 g_al[NN * DD];

// ================= CSR build =================
__global__ void hist_kernel(const int* __restrict__ ei, int E, int* __restrict__ cnt) {
    int i = blockIdx.x * blockDim.x + threadIdx.x;
    if (i < E) atomicAdd(&cnt[ei[E + i]], 1);
}

__global__ void scan_block(const int* __restrict__ cnt, int* __restrict__ offs,
                           int* __restrict__ bsum) {
    __shared__ int sm[SCAN_BS];
    int i = blockIdx.x * SCAN_BS + threadIdx.x;
    int v = (i < NN) ? cnt[i] : 0;
    sm[threadIdx.x] = v;
    __syncthreads();
    #pragma unroll
    for (int d = 1; d < SCAN_BS; d <<= 1) {
        int t = (threadIdx.x >= d) ? sm[threadIdx.x - d] : 0;
        __syncthreads();
        sm[threadIdx.x] += t;
        __syncthreads();
    }
    if (i < NN) offs[i] = sm[threadIdx.x] - v;   // exclusive
    if (threadIdx.x == SCAN_BS - 1) bsum[blockIdx.x] = sm[threadIdx.x];
}

__global__ void scan_top(int* __restrict__ bsum) {
    __shared__ int sm[256];
    int i = threadIdx.x;
    int v = (i < SCAN_NB) ? bsum[i] : 0;
    sm[i] = v;
    __syncthreads();
    #pragma unroll
    for (int d = 1; d < 256; d <<= 1) {
        int t = (i >= d) ? sm[i - d] : 0;
        __syncthreads();
        sm[i] += t;
        __syncthreads();
    }
    if (i < SCAN_NB) bsum[i] = sm[i] - v;        // exclusive
}

__global__ void scan_add(int* __restrict__ offs, const int* __restrict__ bsum,
                         int* __restrict__ cursor, int E) {
    int i = blockIdx.x * blockDim.x + threadIdx.x;
    if (i < NN) {
        int v = offs[i] + bsum[i / SCAN_BS];
        offs[i] = v;
        cursor[i] = v;
    }
    if (i == 0) offs[NN] = E;
}

__global__ void fill_kernel(const int* __restrict__ ei, int E,
                            int* __restrict__ cursor, int* __restrict__ csr) {
    int e = blockIdx.x * blockDim.x + threadIdx.x;
    if (e < E) {
        int pos = atomicAdd(&cursor[ei[E + e]], 1);
        csr[pos] = ei[e];
    }
}

// ================= operand split helpers =================
__device__ __forceinline__ void split_bf16(float v, unsigned short& h, unsigned short& l) {
    __nv_bfloat16 hi = __float2bfloat16(v);
    h = __bfloat16_as_ushort(hi);
    l = __bfloat16_as_ushort(__float2bfloat16(v - __bfloat162float(hi)));
}

// x (fp32) -> Ah/Al bf16 split, one float4 per thread
__global__ void convx_kernel(const float* __restrict__ x,
                             __nv_bfloat16* __restrict__ Ah, __nv_bfloat16* __restrict__ Al) {
    int idx4 = blockIdx.x * blockDim.x + threadIdx.x;
    if (idx4 >= NN * 32) return;
    float4 v = __ldg((const float4*)x + idx4);
    unsigned short h[4], l[4];
    split_bf16(v.x, h[0], l[0]); split_bf16(v.y, h[1], l[1]);
    split_bf16(v.z, h[2], l[2]); split_bf16(v.w, h[3], l[3]);
    uint2 uh = {(uint32_t)h[0] | ((uint32_t)h[1] << 16), (uint32_t)h[2] | ((uint32_t)h[3] << 16)};
    uint2 ul = {(uint32_t)l[0] | ((uint32_t)l[1] << 16), (uint32_t)l[2] | ((uint32_t)l[3] << 16)};
    *(uint2*)&Ah[idx4 * 4] = uh;
    *(uint2*)&Al[idx4 * 4] = ul;
}

// ================ persistent dual GEMM via bf16 tensor cores (split precision) ================
#define AST 136
#define BST 136
#define A_ELEMS (64 * AST)                         // 8704
#define BH_ELEMS (128 * BST)                       // 17408 bf16 per half = 2176 uint4
#define SM_AH 0
#define SM_AL A_ELEMS
#define SM_BH (2 * A_ELEMS)
#define SM_BL (2 * A_ELEMS + BH_ELEMS)
#define MMA_SMEM_BF16 (2 * A_ELEMS + 2 * BH_ELEMS) // 52224 elems
#define MMA_SMEM_BYTES (MMA_SMEM_BF16 * 2)         // 104448 bytes -> 2 blocks/SM
#define GEMM_GRID 296                              // 2 blocks x 148 SMs

// pre-converted weights ([n*BST + k], n<128 Wl, n>=128 Wr)
__device__ __nv_bfloat16 g_wh[256 * BST];
__device__ __nv_bfloat16 g_wlo[256 * BST];

__global__ void convw_kernel(const float* __restrict__ Wl, const float* __restrict__ Wr,
                             __nv_bfloat16* __restrict__ Wh, __nv_bfloat16* __restrict__ Wlo) {
    int i = blockIdx.x * blockDim.x + threadIdx.x;  // 0..32767
    if (i >= 256 * 128) return;
    int n = i >> 7, k = i & 127;
    float w = (n < 128) ? Wl[i] : Wr[i - 16384];
    __nv_bfloat16 hi = __float2bfloat16(w);
    Wh[n * BST + k]  = hi;
    Wlo[n * BST + k] = __float2bfloat16(w - __bfloat162float(hi));
}

__device__ __forceinline__ void mma_bf16(float& c0, float& c1, float& c2, float& c3,
                                         uint32_t a0, uint32_t a1, uint32_t a2, uint32_t a3,
                                         uint32_t b0, uint32_t b1) {
    asm volatile(
        "mma.sync.aligned.m16n8k16.row.col.f32.bf16.bf16.f32 "
        "{%0,%1,%2,%3}, {%4,%5,%6,%7}, {%8,%9}, {%0,%1,%2,%3};"
        : "+f"(c0), "+f"(c1), "+f"(c2), "+f"(c3)
        : "r"(a0), "r"(a1), "r"(a2), "r"(a3), "r"(b0), "r"(b1));
}

// Persistent: each block owns one N-half (even blockIdx -> Y/Wl, odd -> Z/Wr+bias),
// loads its weight half into smem ONCE, then grid-strides over 64-row A tiles.
__global__ __launch_bounds__(256, 2) void gemm_persist(
    const __nv_bfloat16* __restrict__ Ah, const __nv_bfloat16* __restrict__ Al,
    const __nv_bfloat16* __restrict__ Wh, const __nv_bfloat16* __restrict__ Wlo,
    const float* __restrict__ bl,
    float* __restrict__ Y, float* __restrict__ Z, int nrows, int ntiles)
{
    extern __shared__ __nv_bfloat16 sb[];
    __nv_bfloat16* sAh = sb + SM_AH;
    __nv_bfloat16* sAl = sb + SM_AL;
    __nv_bfloat16* sBh = sb + SM_BH;
    __nv_bfloat16* sBl = sb + SM_BL;

    const int tid = threadIdx.x;
    const int half = blockIdx.x & 1;

    // ---- weights once: 2176 uint4 per buffer ----
    {
        const uint4* whg = (const uint4*)(Wh + half * BH_ELEMS);
        const uint4* wlg = (const uint4*)(Wlo + half * BH_ELEMS);
        uint4* sbh4 = (uint4*)sBh;
        uint4* sbl4 = (uint4*)sBl;
        #pragma unroll
        for (int j = 0; j < 9; j++) {
            int idx = tid + 256 * j;
            if (idx < BH_ELEMS / 8) {
                sbh4[idx] = whg[idx];
                sbl4[idx] = wlg[idx];
            }
        }
    }

    const int lane = tid & 31, wid = tid >> 5;
    const int wm = wid & 1, wn = wid >> 1;       // 2 warps along M, 4 along N
    const int m_base = wm * 32, n_base = wn * 32;
    const int g = lane >> 2, c2 = (lane & 3) * 2;
    float* O = half ? Z : Y;

    const uint4 zero4 = {0u, 0u, 0u, 0u};
    const int tile_stride = gridDim.x >> 1;

    for (int tile = blockIdx.x >> 1; tile < ntiles; tile += tile_stride) {
        const int row0 = tile * 64;

        // ---- A tile copy: 1024 uint4 per buffer (flat, pre-converted) ----
        {
            const uint4* ahg = (const uint4*)Ah;
            const uint4* alg = (const uint4*)Al;
            uint4* sah4 = (uint4*)sAh;
            uint4* sal4 = (uint4*)sAl;
            #pragma unroll
            for (int j = 0; j < 4; j++) {
                int idx = tid + 256 * j;        // 0..1023
                int r = idx >> 4, q = idx & 15; // row, 16B chunk (row = 16 uint4)
                int row = row0 + r;
                int dst = r * 17 + q;           // AST=136 bf16 = 17 uint4 per row
                if (row < nrows) {
                    sah4[dst] = ahg[(long long)row * 16 + q];
                    sal4[dst] = alg[(long long)row * 16 + q];
                } else {
                    sah4[dst] = zero4;
                    sal4[dst] = zero4;
                }
            }
        }
        __syncthreads();

        float acc[2][4][4];
        #pragma unroll
        for (int mt = 0; mt < 2; mt++)
            #pragma unroll
            for (int nt = 0; nt < 4; nt++)
                #pragma unroll
                for (int u = 0; u < 4; u++) acc[mt][nt][u] = 0.0f;

        #pragma unroll
        for (int ks = 0; ks < 24; ks++) {
            const int seg = ks >> 3;
            const int k0 = (ks & 7) * 16;
            const __nv_bfloat16* As = (seg == 1) ? sAl : sAh;
            const __nv_bfloat16* Bs = (seg == 2) ? sBl : sBh;

            uint32_t a[2][4];
            #pragma unroll
            for (int mt = 0; mt < 2; mt++) {
                int base = (m_base + mt * 16 + g) * AST + k0 + c2;
                a[mt][0] = *(const uint32_t*)&As[base];
                a[mt][1] = *(const uint32_t*)&As[base + 8 * AST];
                a[mt][2] = *(const uint32_t*)&As[base + 8];
                a[mt][3] = *(const uint32_t*)&As[base + 8 * AST + 8];
            }

            #pragma unroll
            for (int nt = 0; nt < 4; nt++) {
                const __nv_bfloat16* bp = &Bs[(n_base + nt * 8 + g) * BST + k0 + c2];
                uint32_t b0 = *(const uint32_t*)bp;
                uint32_t b1 = *(const uint32_t*)(bp + 8);
                mma_bf16(acc[0][nt][0], acc[0][nt][1], acc[0][nt][2], acc[0][nt][3],
                         a[0][0], a[0][1], a[0][2], a[0][3], b0, b1);
                mma_bf16(acc[1][nt][0], acc[1][nt][1], acc[1][nt][2], acc[1][nt][3],
                         a[1][0], a[1][1], a[1][2], a[1][3], b0, b1);
            }
        }

        // ---- epilogue ----
        #pragma unroll
        for (int mt = 0; mt < 2; mt++) {
            const int row_a = row0 + m_base + mt * 16 + g;
            const int row_b = row_a + 8;
            #pragma unroll
            for (int nt = 0; nt < 4; nt++) {
                int col = n_base + nt * 8 + c2;
                float b0v = 0.0f, b1v = 0.0f;
                if (half) { b0v = __ldg(&bl[col]); b1v = __ldg(&bl[col + 1]); }
                if (row_a < nrows) {
                    float2 v = {acc[0][nt][0 + 0] + b0v, acc[0][nt][1] + b1v};
                    v.x = acc[mt][nt][0] + b0v; v.y = acc[mt][nt][1] + b1v;
                    int row = row0 + m_base + mt * 16 + g;
                    *(float2*)&O[(long long)row * 128 + col] = v;
                }
                if (row_b < nrows) {
                    float2 v = {acc[mt][nt][2] + b0v, acc[mt][nt][3] + b1v};
                    *(float2*)&O[(long long)row_b * 128 + col] = v;
                }
            }
        }
        __syncthreads();   // protect smem A before next tile's copy
    }
}

// ---------------- small GEMM for layer 2 (A from bf16 hi/lo) ----------------
__global__ __launch_bounds__(256) void gemm_small(
    const __nv_bfloat16* __restrict__ Ah, const __nv_bfloat16* __restrict__ Al,
    const float* __restrict__ Wl, const float* __restrict__ Wr, const float* __restrict__ bl,
    float* __restrict__ Y, float* __restrict__ Z)
{
    __shared__ float sW[128 * 16];
    __shared__ float sH[16 * 128];

    const int tid = threadIdx.x;
    #pragma unroll
    for (int j = 0; j < 8; j++) {
        int idx = tid + 256 * j;
        int o = idx & 15, k = idx >> 4;
        sW[k * 16 + o] = (o < 8) ? Wl[o * 128 + k] : Wr[(o - 8) * 128 + k];
    }
    const int row0 = blockIdx.x * 16;
    #pragma unroll
    for (int j = 0; j < 8; j++) {
        int idx = tid + 256 * j;
        int r = idx >> 7, k = idx & 127;
        int row = row0 + r;
        float v = 0.0f;
        if (row < NN) {
            long long off = (long long)row * 128 + k;
            v = __bfloat162float(Ah[off]) + __bfloat162float(Al[off]);
        }
        sH[r * 128 + k] = v;
    }
    __syncthreads();

    const int o = tid & 15, rl = tid >> 4;
    float acc = 0.0f;
    #pragma unroll 8
    for (int k = 0; k < 128; k++)
        acc = fmaf(sH[rl * 128 + k], sW[k * 16 + o], acc);

    int row = row0 + rl;
    if (row < NN) {
        if (o < 8) Y[row * 8 + o] = acc;
        else       Z[row * 8 + (o - 8)] = acc + __ldg(&bl[o - 8]);
    }
}

// ========== gather aggregate d=128: writes bf16 hi/lo (next layer's A) ==========
__global__ __launch_bounds__(256) void gather128(
    const int* __restrict__ csr, const int* __restrict__ offs,
    const float* __restrict__ Y, const float* __restrict__ Z,
    __nv_bfloat16* __restrict__ Ah, __nv_bfloat16* __restrict__ Al)
{
    int node = blockIdx.x * 8 + (threadIdx.x >> 5);
    if (node >= NN) return;
    int lane = threadIdx.x & 31;
    int beg = offs[node], end = offs[node + 1];

    float4 acc = {0.0f, 0.0f, 0.0f, 0.0f};
    const float4* Y4 = (const float4*)Y;

    for (int j = beg; j < end; j += 32) {
        int chunk = min(32, end - j);
        int id = (lane < chunk) ? csr[j + lane] : 0;
        int t = 0;
        for (; t + 4 <= chunk; t += 4) {
            int s0 = __shfl_sync(0xffffffffu, id, t);
            int s1 = __shfl_sync(0xffffffffu, id, t + 1);
            int s2 = __shfl_sync(0xffffffffu, id, t + 2);
            int s3 = __shfl_sync(0xffffffffu, id, t + 3);
            float4 v0 = __ldg(Y4 + s0 * 32 + lane);
            float4 v1 = __ldg(Y4 + s1 * 32 + lane);
            float4 v2 = __ldg(Y4 + s2 * 32 + lane);
            float4 v3 = __ldg(Y4 + s3 * 32 + lane);
            acc.x += v0.x + v1.x + v2.x + v3.x;
            acc.y += v0.y + v1.y + v2.y + v3.y;
            acc.z += v0.z + v1.z + v2.z + v3.z;
            acc.w += v0.w + v1.w + v2.w + v3.w;
        }
        for (; t < chunk; t++) {
            int s = __shfl_sync(0xffffffffu, id, t);
            float4 v = __ldg(Y4 + s * 32 + lane);
            acc.x += v.x; acc.y += v.y; acc.z += v.z; acc.w += v.w;
        }
    }

    float iv = 1.0f / (float)max(end - beg, 1);
    float4 z = __ldg((const float4*)Z + node * 32 + lane);
    float4 v;
    v.x = fmaxf(fmaf(acc.x, iv, z.x), 0.0f);
    v.y = fmaxf(fmaf(acc.y, iv, z.y), 0.0f);
    v.z = fmaxf(fmaf(acc.z, iv, z.z), 0.0f);
    v.w = fmaxf(fmaf(acc.w, iv, z.w), 0.0f);

    unsigned short h[4], l[4];
    split_bf16(v.x, h[0], l[0]); split_bf16(v.y, h[1], l[1]);
    split_bf16(v.z, h[2], l[2]); split_bf16(v.w, h[3], l[3]);
    uint2 uh = {(uint32_t)h[0] | ((uint32_t)h[1] << 16), (uint32_t)h[2] | ((uint32_t)h[3] << 16)};
    uint2 ul = {(uint32_t)l[0] | ((uint32_t)l[1] << 16), (uint32_t)l[2] | ((uint32_t)l[3] << 16)};
    long long base = (long long)node * 128 + lane * 4;
    *(uint2*)&Ah[base] = uh;
    *(uint2*)&Al[base] = ul;
}

// ========== gather d=8 + finalize + log_softmax ==========
__global__ __launch_bounds__(256) void gather8(
    const int* __restrict__ csr, const int* __restrict__ offs,
    const float* __restrict__ Y, const float* __restrict__ Z,
    float* __restrict__ outh, float* __restrict__ outls)
{
    int node = blockIdx.x * 64 + (threadIdx.x >> 2);
    if (node >= NN) return;
    int lane4 = threadIdx.x & 3;
    int beg = offs[node], end = offs[node + 1];

    float a[8] = {0, 0, 0, 0, 0, 0, 0, 0};
    const float4* Y4 = (const float4*)Y;
    for (int j = beg + lane4; j < end; j += 4) {
        int s = csr[j];
        float4 v0 = __ldg(Y4 + s * 2);
        float4 v1 = __ldg(Y4 + s * 2 + 1);
        a[0] += v0.x; a[1] += v0.y; a[2] += v0.z; a[3] += v0.w;
        a[4] += v1.x; a[5] += v1.y; a[6] += v1.z; a[7] += v1.w;
    }
    #pragma unroll
    for (int i = 0; i < 8; i++) {
        a[i] += __shfl_xor_sync(0xffffffffu, a[i], 1);
        a[i] += __shfl_xor_sync(0xffffffffu, a[i], 2);
    }
    if (lane4 != 0) return;

    float iv = 1.0f / (float)max(end - beg, 1);
    float4 z0 = __ldg((const float4*)Z + node * 2);
    float4 z1 = __ldg((const float4*)Z + node * 2 + 1);
    float h[8];
    h[0] = fmaf(a[0], iv, z0.x); h[1] = fmaf(a[1], iv, z0.y);
    h[2] = fmaf(a[2], iv, z0.z); h[3] = fmaf(a[3], iv, z0.w);
    h[4] = fmaf(a[4], iv, z1.x); h[5] = fmaf(a[5], iv, z1.y);
    h[6] = fmaf(a[6], iv, z1.z); h[7] = fmaf(a[7], iv, z1.w);

    ((float4*)outh)[node * 2]     = make_float4(h[0], h[1], h[2], h[3]);
    ((float4*)outh)[node * 2 + 1] = make_float4(h[4], h[5], h[6], h[7]);

    if (outls) {
        float m = h[0];
        #pragma unroll
        for (int j = 1; j < 8; j++) m = fmaxf(m, h[j]);
        float sum = 0.0f;
        #pragma unroll
        for (int j = 0; j < 8; j++) sum += expf(h[j] - m);
        float lse = logf(sum) + m;
        ((float4*)outls)[node * 2]     = make_float4(h[0]-lse, h[1]-lse, h[2]-lse, h[3]-lse);
        ((float4*)outls)[node * 2 + 1] = make_float4(h[4]-lse, h[5]-lse, h[6]-lse, h[7]-lse);
    }
}

// ---------------- launch ----------------
extern "C" void kernel_launch(void* const* d_in, const int* in_sizes, int n_in,
                              void* d_out, int out_size)
{
    const float* x   = (const float*)d_in[0];
    const int*   ei  = (const int*)d_in[1];   // int32 (JAX default downcasts int64)
    const float* Wl0 = (const float*)d_in[2];
    const float* bl0 = (const float*)d_in[3];
    const float* Wr0 = (const float*)d_in[4];
    const float* Wl1 = (const float*)d_in[5];
    const float* bl1 = (const float*)d_in[6];
    const float* Wr1 = (const float*)d_in[7];
    const float* Wl2 = (const float*)d_in[8];
    const float* bl2 = (const float*)d_in[9];
    const float* Wr2 = (const float*)d_in[10];
    int E = in_sizes[1] / 2;
    if (E > EMAX) E = EMAX;
    float* out = (float*)d_out;

    void *py, *pz, *py2, *pz2, *pcnt, *poffs, *pcur, *pbsum, *pcsr, *pwh, *pwl, *pah, *pal;
    cudaGetSymbolAddress(&py,   g_y);
    cudaGetSymbolAddress(&pz,   g_z);
    cudaGetSymbolAddress(&py2,  g_y2);
    cudaGetSymbolAddress(&pz2,  g_z2);
    cudaGetSymbolAddress(&pcnt, g_cnt);
    cudaGetSymbolAddress(&poffs,g_offs);
    cudaGetSymbolAddress(&pcur, g_cursor);
    cudaGetSymbolAddress(&pbsum,g_bsum);
    cudaGetSymbolAddress(&pcsr, g_csr);
    cudaGetSymbolAddress(&pwh,  g_wh);
    cudaGetSymbolAddress(&pwl,  g_wlo);
    cudaGetSymbolAddress(&pah,  g_ah);
    cudaGetSymbolAddress(&pal,  g_al);

    cudaFuncSetAttribute(gemm_persist, cudaFuncAttributeMaxDynamicSharedMemorySize, MMA_SMEM_BYTES);

    __nv_bfloat16* Ah = (__nv_bfloat16*)pah;
    __nv_bfloat16* Al = (__nv_bfloat16*)pal;
    const __nv_bfloat16* Wh = (const __nv_bfloat16*)pwh;
    const __nv_bfloat16* Wlo = (const __nv_bfloat16*)pwl;

    // ---- build CSR (dst-major) ----
    cudaMemsetAsync(pcnt, 0, NN * sizeof(int));
    hist_kernel<<<(E + 255) / 256, 256>>>(ei, E, (int*)pcnt);
    scan_block<<<SCAN_NB, SCAN_BS>>>((const int*)pcnt, (int*)poffs, (int*)pbsum);
    scan_top<<<1, 256>>>((int*)pbsum);
    scan_add<<<(NN + 255) / 256, 256>>>((int*)poffs, (const int*)pbsum, (int*)pcur, E);
    fill_kernel<<<(E + 255) / 256, 256>>>(ei, E, (int*)pcur, (int*)pcsr);

    // ---- layer 0: x -> h1 (bf16 split in Ah/Al) ----
    convx_kernel<<<(NN * 32 + 255) / 256, 256>>>(x, Ah, Al);
    convw_kernel<<<128, 256>>>(Wl0, Wr0, (__nv_bfloat16*)pwh, (__nv_bfloat16*)pwl);
    gemm_persist<<<GEMM_GRID, 256, MMA_SMEM_BYTES>>>(Ah, Al, Wh, Wlo, bl0,
                                                     (float*)py, (float*)pz, NN, NTILES);
    gather128<<<(NN + 7) / 8, 256>>>((const int*)pcsr, (const int*)poffs,
                                     (const float*)py, (const float*)pz, Ah, Al);

    // ---- layer 1: h1 -> h2 ----
    convw_kernel<<<128, 256>>>(Wl1, Wr1, (__nv_bfloat16*)pwh, (__nv_bfloat16*)pwl);
    gemm_persist<<<GEMM_GRID, 256, MMA_SMEM_BYTES>>>(Ah, Al, Wh, Wlo, bl1,
                                                     (float*)py, (float*)pz, NN, NTILES);
    gather128<<<(NN + 7) / 8, 256>>>((const int*)pcsr, (const int*)poffs,
                                     (const float*)py, (const float*)pz, Ah, Al);

    // ---- layer 2: h2 -> out ----
    gemm_small<<<(NN + 15) / 16, 256>>>(Ah, Al, Wl2, Wr2, bl2, (float*)py2, (float*)pz2);
    float* outls = (out_size >= 2 * NN * DOUT) ? (out + (size_t)NN * DOUT) : nullptr;
    gather8<<<(NN + 63) / 64, 256>>>((const int*)pcsr, (const int*)poffs,
                                     (const float*)py2, (const float*)pz2, out, outls);
}

// round 12
// speedup vs baseline: 1.2528x; 1.1500x over previous
#include <cuda_runtime.h>
#include <cuda_bf16.h>
#include <cstdint>
#include <math.h>

#define NN 100000
#define DD 128
#define DOUT 8
#define EMAX 1600000
#define SCAN_BS 512
#define SCAN_NB ((NN + SCAN_BS - 1) / SCAN_BS)   // 196
#define NTILES ((NN + 63) / 64)                  // 1563
#define GEMM_GRID 148                            // persistent, 1 block/SM

// ---------------- scratch (static device globals; no allocation) ----------------
__device__ float g_y[NN * DD];
__device__ float g_z[NN * DD];
__device__ float g_y2[NN * DOUT];
__device__ float g_z2[NN * DOUT];
__device__ int   g_cnt[NN];
__device__ int   g_offs[NN + 1];
__device__ int   g_cursor[NN];
__device__ int   g_bsum[SCAN_NB];
__device__ int   g_csr[EMAX];
// bf16 hi/lo operand arrays for GEMM A (x, then h1, then h2), layout [row*128 + k]
__device__ __nv_bfloat16 g_ah[NN * DD];
__device__ __nv_bfloat16 g_al[NN * DD];

// ================= CSR build =================
__global__ void hist_kernel(const int* __restrict__ ei, int E, int* __restrict__ cnt) {
    int i = blockIdx.x * blockDim.x + threadIdx.x;
    if (i < E) atomicAdd(&cnt[ei[E + i]], 1);
}

__global__ void scan_block(const int* __restrict__ cnt, int* __restrict__ offs,
                           int* __restrict__ bsum) {
    __shared__ int sm[SCAN_BS];
    int i = blockIdx.x * SCAN_BS + threadIdx.x;
    int v = (i < NN) ? cnt[i] : 0;
    sm[threadIdx.x] = v;
    __syncthreads();
    #pragma unroll
    for (int d = 1; d < SCAN_BS; d <<= 1) {
        int t = (threadIdx.x >= d) ? sm[threadIdx.x - d] : 0;
        __syncthreads();
        sm[threadIdx.x] += t;
        __syncthreads();
    }
    if (i < NN) offs[i] = sm[threadIdx.x] - v;   // exclusive
    if (threadIdx.x == SCAN_BS - 1) bsum[blockIdx.x] = sm[threadIdx.x];
}

__global__ void scan_top(int* __restrict__ bsum) {
    __shared__ int sm[256];
    int i = threadIdx.x;
    int v = (i < SCAN_NB) ? bsum[i] : 0;
    sm[i] = v;
    __syncthreads();
    #pragma unroll
    for (int d = 1; d < 256; d <<= 1) {
        int t = (i >= d) ? sm[i - d] : 0;
        __syncthreads();
        sm[i] += t;
        __syncthreads();
    }
    if (i < SCAN_NB) bsum[i] = sm[i] - v;        // exclusive
}

__global__ void scan_add(int* __restrict__ offs, const int* __restrict__ bsum,
                         int* __restrict__ cursor, int E) {
    int i = blockIdx.x * blockDim.x + threadIdx.x;
    if (i < NN) {
        int v = offs[i] + bsum[i / SCAN_BS];
        offs[i] = v;
        cursor[i] = v;
    }
    if (i == 0) offs[NN] = E;
}

__global__ void fill_kernel(const int* __restrict__ ei, int E,
                            int* __restrict__ cursor, int* __restrict__ csr) {
    int e = blockIdx.x * blockDim.x + threadIdx.x;
    if (e < E) {
        int pos = atomicAdd(&cursor[ei[E + e]], 1);
        csr[pos] = ei[e];
    }
}

// ================= operand split helpers =================
__device__ __forceinline__ void split_bf16(float v, unsigned short& h, unsigned short& l) {
    __nv_bfloat16 hi = __float2bfloat16(v);
    h = __bfloat16_as_ushort(hi);
    l = __bfloat16_as_ushort(__float2bfloat16(v - __bfloat162float(hi)));
}

__global__ void convx_kernel(const float* __restrict__ x,
                             __nv_bfloat16* __restrict__ Ah, __nv_bfloat16* __restrict__ Al) {
    int idx4 = blockIdx.x * blockDim.x + threadIdx.x;
    if (idx4 >= NN * 32) return;
    float4 v = __ldg((const float4*)x + idx4);
    unsigned short h[4], l[4];
    split_bf16(v.x, h[0], l[0]); split_bf16(v.y, h[1], l[1]);
    split_bf16(v.z, h[2], l[2]); split_bf16(v.w, h[3], l[3]);
    uint2 uh = {(uint32_t)h[0] | ((uint32_t)h[1] << 16), (uint32_t)h[2] | ((uint32_t)h[3] << 16)};
    uint2 ul = {(uint32_t)l[0] | ((uint32_t)l[1] << 16), (uint32_t)l[2] | ((uint32_t)l[3] << 16)};
    *(uint2*)&Ah[idx4 * 4] = uh;
    *(uint2*)&Al[idx4 * 4] = ul;
}

// ================ persistent dual GEMM, full N=256, cp.async double-buffered A ================
#define AST 136
#define BST 136
#define B_ELEMS (256 * BST)                        // 34816 elems per (hi|lo) weight buffer
#define A_HALF_ELEMS (64 * AST)                    // 8704 elems (one of Ah / Al per stage)
#define A_STAGE_ELEMS (2 * A_HALF_ELEMS)           // 17408 elems per stage (Ah then Al)
#define A_HALF_BYTES (A_HALF_ELEMS * 2)            // 17408 bytes: Al byte offset within stage
#define SM_BH 0
#define SM_BL B_ELEMS
#define SM_A0 (2 * B_ELEMS)                        // stage 0 (elems)
#define SM_A1 (2 * B_ELEMS + A_STAGE_ELEMS)        // stage 1 (elems)
#define MMA_SMEM_BF16 (2 * B_ELEMS + 2 * A_STAGE_ELEMS)  // 104448 elems
#define MMA_SMEM_BYTES (MMA_SMEM_BF16 * 2)         // 208896 bytes

// pre-converted weights ([n*BST + k], n<128 Wl, n>=128 Wr)
__device__ __nv_bfloat16 g_wh[256 * BST];
__device__ __nv_bfloat16 g_wlo[256 * BST];

__global__ void convw_kernel(const float* __restrict__ Wl, const float* __restrict__ Wr,
                             __nv_bfloat16* __restrict__ Wh, __nv_bfloat16* __restrict__ Wlo) {
    int i = blockIdx.x * blockDim.x + threadIdx.x;  // 0..32767
    if (i >= 256 * 128) return;
    int n = i >> 7, k = i & 127;
    float w = (n < 128) ? Wl[i] : Wr[i - 16384];
    __nv_bfloat16 hi = __float2bfloat16(w);
    Wh[n * BST + k]  = hi;
    Wlo[n * BST + k] = __float2bfloat16(w - __bfloat162float(hi));
}

__device__ __forceinline__ void mma_bf16(float& c0, float& c1, float& c2, float& c3,
                                         uint32_t a0, uint32_t a1, uint32_t a2, uint32_t a3,
                                         uint32_t b0, uint32_t b1) {
    asm volatile(
        "mma.sync.aligned.m16n8k16.row.col.f32.bf16.bf16.f32 "
        "{%0,%1,%2,%3}, {%4,%5,%6,%7}, {%8,%9}, {%0,%1,%2,%3};"
        : "+f"(c0), "+f"(c1), "+f"(c2), "+f"(c3)
        : "r"(a0), "r"(a1), "r"(a2), "r"(a3), "r"(b0), "r"(b1));
}

__device__ __forceinline__ void cpa16(uint32_t dst_smem, const void* src, uint32_t src_bytes) {
    asm volatile("cp.async.cg.shared.global [%0], [%1], 16, %2;"
                 :: "r"(dst_smem), "l"(src), "r"(src_bytes) : "memory");
}

// Issue async copy of A tile (64 rows x 128 cols, hi+lo) into the given stage.
// Stage layout (bytes): [0, A_HALF_BYTES) = Ah rows (17 uint4/row), [A_HALF_BYTES, 2*A_HALF_BYTES) = Al.
__device__ __forceinline__ void issue_a_copy(
    uint32_t stage_base_smem,                     // smem byte addr of stage start (Ah)
    const __nv_bfloat16* __restrict__ Ah, const __nv_bfloat16* __restrict__ Al,
    int row0, int nrows, int tid)
{
    // 1024 uint4 per buffer: idx -> r = idx>>4, q = idx&15; dst uint4 = r*17 + q
    #pragma unroll
    for (int j = 0; j < 4; j++) {
        int idx = tid + 256 * j;
        int r = idx >> 4, q = idx & 15;
        int row = row0 + r;
        int ok = (row < nrows);
        long long src_off = (long long)(ok ? row : 0) * 128 + q * 8;  // elems
        uint32_t dst = stage_base_smem + (uint32_t)(r * 17 + q) * 16;
        cpa16(dst, Ah + src_off, ok ? 16u : 0u);
        cpa16(dst + A_HALF_BYTES, Al + src_off, ok ? 16u : 0u);
    }
    asm volatile("cp.async.commit_group;" ::: "memory");
}

__global__ __launch_bounds__(256, 1) void gemm_persist(
    const __nv_bfloat16* __restrict__ Ah, const __nv_bfloat16* __restrict__ Al,
    const __nv_bfloat16* __restrict__ Wh, const __nv_bfloat16* __restrict__ Wlo,
    const float* __restrict__ bl,
    float* __restrict__ Y, float* __restrict__ Z, int nrows, int ntiles)
{
    extern __shared__ __nv_bfloat16 sb[];
    __nv_bfloat16* sBh = sb + SM_BH;
    __nv_bfloat16* sBl = sb + SM_BL;

    const int tid = threadIdx.x;
    uint32_t smem_base;
    {
        void* p = sb;
        smem_base = (uint32_t)__cvta_generic_to_shared(p);
    }
    const uint32_t stage_addr[2] = {smem_base + SM_A0 * 2, smem_base + SM_A1 * 2};

    // ---- weights once: 4352 uint4 per buffer (17 x 256) ----
    {
        const uint4* whg = (const uint4*)Wh;
        const uint4* wlg = (const uint4*)Wlo;
        uint4* sbh4 = (uint4*)sBh;
        uint4* sbl4 = (uint4*)sBl;
        #pragma unroll
        for (int j = 0; j < 17; j++) {
            int idx = tid + 256 * j;
            sbh4[idx] = whg[idx];
            sbl4[idx] = wlg[idx];
        }
    }

    const int lane = tid & 31, wid = tid >> 5;
    const int wm = wid & 3, wn = wid >> 2;       // 4 warps along M, 2 along N
    const int m_base = wm * 16, n_base = wn * 128;
    const int g = lane >> 2, c2 = (lane & 3) * 2;

    const int t0 = blockIdx.x;
    int s = 0;
    if (t0 < ntiles)
        issue_a_copy(stage_addr[0], Ah, Al, t0 * 64, nrows, tid);

    for (int tile = t0; tile < ntiles; tile += GEMM_GRID, s ^= 1) {
        asm volatile("cp.async.wait_group 0;" ::: "memory");
        __syncthreads();                          // stage s ready; prev readers of s^1 done

        int next = tile + GEMM_GRID;
        if (next < ntiles)
            issue_a_copy(stage_addr[s ^ 1], Ah, Al, next * 64, nrows, tid);

        const __nv_bfloat16* sAh = sb + (s ? SM_A1 : SM_A0);
        const __nv_bfloat16* sAl = sAh + A_HALF_ELEMS;   // Al is half a stage in, NOT a full stage
        const int row0 = tile * 64;

        float acc[16][4];
        #pragma unroll
        for (int nt = 0; nt < 16; nt++)
            #pragma unroll
            for (int u = 0; u < 4; u++) acc[nt][u] = 0.0f;

        #pragma unroll
        for (int ks = 0; ks < 24; ks++) {
            const int seg = ks >> 3;
            const int k0 = (ks & 7) * 16;
            const __nv_bfloat16* As = (seg == 1) ? sAl : sAh;
            const __nv_bfloat16* Bs = (seg == 2) ? sBl : sBh;

            int abase = (m_base + g) * AST + k0 + c2;
            uint32_t a0 = *(const uint32_t*)&As[abase];
            uint32_t a1 = *(const uint32_t*)&As[abase + 8 * AST];
            uint32_t a2 = *(const uint32_t*)&As[abase + 8];
            uint32_t a3 = *(const uint32_t*)&As[abase + 8 * AST + 8];

            #pragma unroll
            for (int nt = 0; nt < 16; nt++) {
                const __nv_bfloat16* bp = &Bs[(n_base + nt * 8 + g) * BST + k0 + c2];
                uint32_t b0 = *(const uint32_t*)bp;
                uint32_t b1 = *(const uint32_t*)(bp + 8);
                mma_bf16(acc[nt][0], acc[nt][1], acc[nt][2], acc[nt][3],
                         a0, a1, a2, a3, b0, b1);
            }
        }

        // ---- epilogue: n<128 -> Y, n>=128 -> Z (+bias) ----
        const int row_a = row0 + m_base + g;
        const int row_b = row_a + 8;
        #pragma unroll
        for (int nt = 0; nt < 16; nt++) {
            int n = n_base + nt * 8 + c2;
            float b0v = 0.0f, b1v = 0.0f;
            float* O;
            int col;
            if (n < 128) { O = Y; col = n; }
            else { O = Z; col = n - 128; b0v = __ldg(&bl[col]); b1v = __ldg(&bl[col + 1]); }
            if (row_a < nrows) {
                float2 v = {acc[nt][0] + b0v, acc[nt][1] + b1v};
                *(float2*)&O[(long long)row_a * 128 + col] = v;
            }
            if (row_b < nrows) {
                float2 v = {acc[nt][2] + b0v, acc[nt][3] + b1v};
                *(float2*)&O[(long long)row_b * 128 + col] = v;
            }
        }
    }
}

// ---------------- small GEMM for layer 2 (A from bf16 hi/lo) ----------------
__global__ __launch_bounds__(256) void gemm_small(
    const __nv_bfloat16* __restrict__ Ah, const __nv_bfloat16* __restrict__ Al,
    const float* __restrict__ Wl, const float* __restrict__ Wr, const float* __restrict__ bl,
    float* __restrict__ Y, float* __restrict__ Z)
{
    __shared__ float sW[128 * 16];
    __shared__ float sH[16 * 128];

    const int tid = threadIdx.x;
    #pragma unroll
    for (int j = 0; j < 8; j++) {
        int idx = tid + 256 * j;
        int o = idx & 15, k = idx >> 4;
        sW[k * 16 + o] = (o < 8) ? Wl[o * 128 + k] : Wr[(o - 8) * 128 + k];
    }
    const int row0 = blockIdx.x * 16;
    #pragma unroll
    for (int j = 0; j < 8; j++) {
        int idx = tid + 256 * j;
        int r = idx >> 7, k = idx & 127;
        int row = row0 + r;
        float v = 0.0f;
        if (row < NN) {
            long long off = (long long)row * 128 + k;
            v = __bfloat162float(Ah[off]) + __bfloat162float(Al[off]);
        }
        sH[r * 128 + k] = v;
    }
    __syncthreads();

    const int o = tid & 15, rl = tid >> 4;
    float acc = 0.0f;
    #pragma unroll 8
    for (int k = 0; k < 128; k++)
        acc = fmaf(sH[rl * 128 + k], sW[k * 16 + o], acc);

    int row = row0 + rl;
    if (row < NN) {
        if (o < 8) Y[row * 8 + o] = acc;
        else       Z[row * 8 + (o - 8)] = acc + __ldg(&bl[o - 8]);
    }
}

// ========== gather aggregate d=128: writes bf16 hi/lo (next layer's A) ==========
__global__ __launch_bounds__(256) void gather128(
    const int* __restrict__ csr, const int* __restrict__ offs,
    const float* __restrict__ Y, const float* __restrict__ Z,
    __nv_bfloat16* __restrict__ Ah, __nv_bfloat16* __restrict__ Al)
{
    int node = blockIdx.x * 8 + (threadIdx.x >> 5);
    if (node >= NN) return;
    int lane = threadIdx.x & 31;
    int beg = offs[node], end = offs[node + 1];

    float4 acc = {0.0f, 0.0f, 0.0f, 0.0f};
    const float4* Y4 = (const float4*)Y;

    for (int j = beg; j < end; j += 32) {
        int chunk = min(32, end - j);
        int id = (lane < chunk) ? csr[j + lane] : 0;
        int t = 0;
        for (; t + 4 <= chunk; t += 4) {
            int s0 = __shfl_sync(0xffffffffu, id, t);
            int s1 = __shfl_sync(0xffffffffu, id, t + 1);
            int s2 = __shfl_sync(0xffffffffu, id, t + 2);
            int s3 = __shfl_sync(0xffffffffu, id, t + 3);
            float4 v0 = __ldg(Y4 + s0 * 32 + lane);
            float4 v1 = __ldg(Y4 + s1 * 32 + lane);
            float4 v2 = __ldg(Y4 + s2 * 32 + lane);
            float4 v3 = __ldg(Y4 + s3 * 32 + lane);
            acc.x += v0.x + v1.x + v2.x + v3.x;
            acc.y += v0.y + v1.y + v2.y + v3.y;
            acc.z += v0.z + v1.z + v2.z + v3.z;
            acc.w += v0.w + v1.w + v2.w + v3.w;
        }
        for (; t < chunk; t++) {
            int s = __shfl_sync(0xffffffffu, id, t);
            float4 v = __ldg(Y4 + s * 32 + lane);
            acc.x += v.x; acc.y += v.y; acc.z += v.z; acc.w += v.w;
        }
    }

    float iv = 1.0f / (float)max(end - beg, 1);
    float4 z = __ldg((const float4*)Z + node * 32 + lane);
    float4 v;
    v.x = fmaxf(fmaf(acc.x, iv, z.x), 0.0f);
    v.y = fmaxf(fmaf(acc.y, iv, z.y), 0.0f);
    v.z = fmaxf(fmaf(acc.z, iv, z.z), 0.0f);
    v.w = fmaxf(fmaf(acc.w, iv, z.w), 0.0f);

    unsigned short h[4], l[4];
    split_bf16(v.x, h[0], l[0]); split_bf16(v.y, h[1], l[1]);
    split_bf16(v.z, h[2], l[2]); split_bf16(v.w, h[3], l[3]);
    uint2 uh = {(uint32_t)h[0] | ((uint32_t)h[1] << 16), (uint32_t)h[2] | ((uint32_t)h[3] << 16)};
    uint2 ul = {(uint32_t)l[0] | ((uint32_t)l[1] << 16), (uint32_t)l[2] | ((uint32_t)l[3] << 16)};
    long long base = (long long)node * 128 + lane * 4;
    *(uint2*)&Ah[base] = uh;
    *(uint2*)&Al[base] = ul;
}

// ========== gather d=8 + finalize + log_softmax ==========
__global__ __launch_bounds__(256) void gather8(
    const int* __restrict__ csr, const int* __restrict__ offs,
    const float* __restrict__ Y, const float* __restrict__ Z,
    float* __restrict__ outh, float* __restrict__ outls)
{
    int node = blockIdx.x * 64 + (threadIdx.x >> 2);
    if (node >= NN) return;
    int lane4 = threadIdx.x & 3;
    int beg = offs[node], end = offs[node + 1];

    float a[8] = {0, 0, 0, 0, 0, 0, 0, 0};
    const float4* Y4 = (const float4*)Y;
    for (int j = beg + lane4; j < end; j += 4) {
        int s = csr[j];
        float4 v0 = __ldg(Y4 + s * 2);
        float4 v1 = __ldg(Y4 + s * 2 + 1);
        a[0] += v0.x; a[1] += v0.y; a[2] += v0.z; a[3] += v0.w;
        a[4] += v1.x; a[5] += v1.y; a[6] += v1.z; a[7] += v1.w;
    }
    #pragma unroll
    for (int i = 0; i < 8; i++) {
        a[i] += __shfl_xor_sync(0xffffffffu, a[i], 1);
        a[i] += __shfl_xor_sync(0xffffffffu, a[i], 2);
    }
    if (lane4 != 0) return;

    float iv = 1.0f / (float)max(end - beg, 1);
    float4 z0 = __ldg((const float4*)Z + node * 2);
    float4 z1 = __ldg((const float4*)Z + node * 2 + 1);
    float h[8];
    h[0] = fmaf(a[0], iv, z0.x); h[1] = fmaf(a[1], iv, z0.y);
    h[2] = fmaf(a[2], iv, z0.z); h[3] = fmaf(a[3], iv, z0.w);
    h[4] = fmaf(a[4], iv, z1.x); h[5] = fmaf(a[5], iv, z1.y);
    h[6] = fmaf(a[6], iv, z1.z); h[7] = fmaf(a[7], iv, z1.w);

    ((float4*)outh)[node * 2]     = make_float4(h[0], h[1], h[2], h[3]);
    ((float4*)outh)[node * 2 + 1] = make_float4(h[4], h[5], h[6], h[7]);

    if (outls) {
        float m = h[0];
        #pragma unroll
        for (int j = 1; j < 8; j++) m = fmaxf(m, h[j]);
        float sum = 0.0f;
        #pragma unroll
        for (int j = 0; j < 8; j++) sum += expf(h[j] - m);
        float lse = logf(sum) + m;
        ((float4*)outls)[node * 2]     = make_float4(h[0]-lse, h[1]-lse, h[2]-lse, h[3]-lse);
        ((float4*)outls)[node * 2 + 1] = make_float4(h[4]-lse, h[5]-lse, h[6]-lse, h[7]-lse);
    }
}

// ---------------- launch ----------------
extern "C" void kernel_launch(void* const* d_in, const int* in_sizes, int n_in,
                              void* d_out, int out_size)
{
    const float* x   = (const float*)d_in[0];
    const int*   ei  = (const int*)d_in[1];   // int32 (JAX default downcasts int64)
    const float* Wl0 = (const float*)d_in[2];
    const float* bl0 = (const float*)d_in[3];
    const float* Wr0 = (const float*)d_in[4];
    const float* Wl1 = (const float*)d_in[5];
    const float* bl1 = (const float*)d_in[6];
    const float* Wr1 = (const float*)d_in[7];
    const float* Wl2 = (const float*)d_in[8];
    const float* bl2 = (const float*)d_in[9];
    const float* Wr2 = (const float*)d_in[10];
    int E = in_sizes[1] / 2;
    if (E > EMAX) E = EMAX;
    float* out = (float*)d_out;

    void *py, *pz, *py2, *pz2, *pcnt, *poffs, *pcur, *pbsum, *pcsr, *pwh, *pwl, *pah, *pal;
    cudaGetSymbolAddress(&py,   g_y);
    cudaGetSymbolAddress(&pz,   g_z);
    cudaGetSymbolAddress(&py2,  g_y2);
    cudaGetSymbolAddress(&pz2,  g_z2);
    cudaGetSymbolAddress(&pcnt, g_cnt);
    cudaGetSymbolAddress(&poffs,g_offs);
    cudaGetSymbolAddress(&pcur, g_cursor);
    cudaGetSymbolAddress(&pbsum,g_bsum);
    cudaGetSymbolAddress(&pcsr, g_csr);
    cudaGetSymbolAddress(&pwh,  g_wh);
    cudaGetSymbolAddress(&pwl,  g_wlo);
    cudaGetSymbolAddress(&pah,  g_ah);
    cudaGetSymbolAddress(&pal,  g_al);

    cudaFuncSetAttribute(gemm_persist, cudaFuncAttributeMaxDynamicSharedMemorySize, MMA_SMEM_BYTES);

    __nv_bfloat16* Ah = (__nv_bfloat16*)pah;
    __nv_bfloat16* Al = (__nv_bfloat16*)pal;
    const __nv_bfloat16* Wh = (const __nv_bfloat16*)pwh;
    const __nv_bfloat16* Wlo = (const __nv_bfloat16*)pwl;

    // ---- build CSR (dst-major) ----
    cudaMemsetAsync(pcnt, 0, NN * sizeof(int));
    hist_kernel<<<(E + 255) / 256, 256>>>(ei, E, (int*)pcnt);
    scan_block<<<SCAN_NB, SCAN_BS>>>((const int*)pcnt, (int*)poffs, (int*)pbsum);
    scan_top<<<1, 256>>>((int*)pbsum);
    scan_add<<<(NN + 255) / 256, 256>>>((int*)poffs, (const int*)pbsum, (int*)pcur, E);
    fill_kernel<<<(E + 255) / 256, 256>>>(ei, E, (int*)pcur, (int*)pcsr);

    // ---- layer 0: x -> h1 (bf16 split in Ah/Al) ----
    convx_kernel<<<(NN * 32 + 255) / 256, 256>>>(x, Ah, Al);
    convw_kernel<<<128, 256>>>(Wl0, Wr0, (__nv_bfloat16*)pwh, (__nv_bfloat16*)pwl);
    gemm_persist<<<GEMM_GRID, 256, MMA_SMEM_BYTES>>>(Ah, Al, Wh, Wlo, bl0,
                                                     (float*)py, (float*)pz, NN, NTILES);
    gather128<<<(NN + 7) / 8, 256>>>((const int*)pcsr, (const int*)poffs,
                                     (const float*)py, (const float*)pz, Ah, Al);

    // ---- layer 1: h1 -> h2 ----
    convw_kernel<<<128, 256>>>(Wl1, Wr1, (__nv_bfloat16*)pwh, (__nv_bfloat16*)pwl);
    gemm_persist<<<GEMM_GRID, 256, MMA_SMEM_BYTES>>>(Ah, Al, Wh, Wlo, bl1,
                                                     (float*)py, (float*)pz, NN, NTILES);
    gather128<<<(NN + 7) / 8, 256>>>((const int*)pcsr, (const int*)poffs,
                                     (const float*)py, (const float*)pz, Ah, Al);

    // ---- layer 2: h2 -> out ----
    gemm_small<<<(NN + 15) / 16, 256>>>(Ah, Al, Wl2, Wr2, bl2, (float*)py2, (float*)pz2);
    float* outls = (out_size >= 2 * NN * DOUT) ? (out + (size_t)NN * DOUT) : nullptr;
    gather8<<<(NN + 63) / 64, 256>>>((const int*)pcsr, (const int*)poffs,
                                     (const float*)py2, (const float*)pz2, out, outls);
}